// round 4
// baseline (speedup 1.0000x reference)
#include <cuda_runtime.h>
#include <cuda_bf16.h>
#include <cstdint>

// Problem constants (B=2, T=512, C=256, HID=1024)
constexpr int Mrows = 1024;   // B*T
constexpr int Cdim  = 256;
constexpr int Hdim  = 1024;

// Static device scratch
__device__ __nv_bfloat16 g_h2 [Mrows * Cdim];
__device__ __nv_bfloat16 g_hid[Mrows * Hdim];

// ---------------------------------------------------------------------------
// PTX helpers
// ---------------------------------------------------------------------------
__device__ __forceinline__ uint32_t smem_u32(const void* p) {
    return (uint32_t)__cvta_generic_to_shared(p);
}
__device__ __forceinline__ void ldsm_x4(uint32_t& r0, uint32_t& r1,
                                        uint32_t& r2, uint32_t& r3, uint32_t a) {
    asm volatile("ldmatrix.sync.aligned.m8n8.x4.shared.b16 {%0,%1,%2,%3},[%4];"
                 : "=r"(r0), "=r"(r1), "=r"(r2), "=r"(r3) : "r"(a));
}
__device__ __forceinline__ void mma_bf16(float* c, const uint32_t* a, const uint32_t* b) {
    asm volatile(
        "mma.sync.aligned.m16n8k16.row.col.f32.bf16.bf16.f32 "
        "{%0,%1,%2,%3},{%4,%5,%6,%7},{%8,%9},{%0,%1,%2,%3};"
        : "+f"(c[0]), "+f"(c[1]), "+f"(c[2]), "+f"(c[3])
        : "r"(a[0]), "r"(a[1]), "r"(a[2]), "r"(a[3]), "r"(b[0]), "r"(b[1]));
}
__device__ __forceinline__ void cp_async16(uint32_t s, const void* g) {
    asm volatile("cp.async.cg.shared.global [%0], [%1], 16;" :: "r"(s), "l"(g));
}
__device__ __forceinline__ void cp_commit() {
    asm volatile("cp.async.commit_group;");
}
template <int N> __device__ __forceinline__ void cp_wait() {
    asm volatile("cp.async.wait_group %0;" :: "n"(N));
}

// ---------------------------------------------------------------------------
// LN: one warp per row. h2 = LN(x + bp)*g2 + b2  -> bf16
// ---------------------------------------------------------------------------
__global__ void ln_kernel(const float* __restrict__ x,
                          const float* __restrict__ bp,
                          const float* __restrict__ g2,
                          const float* __restrict__ b2)
{
    const int gtid = blockIdx.x * blockDim.x + threadIdx.x;
    const int row  = gtid >> 5;
    const int lane = gtid & 31;
    const int c0   = lane * 8;
    const float* rp = x + (size_t)row * Cdim + c0;

    float v[8];
    {
        const float4 a  = *reinterpret_cast<const float4*>(rp);
        const float4 b  = *reinterpret_cast<const float4*>(rp + 4);
        const float4 pa = *reinterpret_cast<const float4*>(bp + c0);
        const float4 pb = *reinterpret_cast<const float4*>(bp + c0 + 4);
        v[0] = a.x + pa.x; v[1] = a.y + pa.y; v[2] = a.z + pa.z; v[3] = a.w + pa.w;
        v[4] = b.x + pb.x; v[5] = b.y + pb.y; v[6] = b.z + pb.z; v[7] = b.w + pb.w;
    }
    float s = 0.f, q = 0.f;
    #pragma unroll
    for (int j = 0; j < 8; j++) { s += v[j]; q += v[j] * v[j]; }
    #pragma unroll
    for (int o = 16; o > 0; o >>= 1) {
        s += __shfl_xor_sync(0xffffffffu, s, o);
        q += __shfl_xor_sync(0xffffffffu, q, o);
    }
    const float mean = s * (1.0f / Cdim);
    const float var  = q * (1.0f / Cdim) - mean * mean;
    const float inv  = rsqrtf(var + 1e-5f);

    const float4 ga = *reinterpret_cast<const float4*>(g2 + c0);
    const float4 gb = *reinterpret_cast<const float4*>(g2 + c0 + 4);
    const float4 ba = *reinterpret_cast<const float4*>(b2 + c0);
    const float4 bb = *reinterpret_cast<const float4*>(b2 + c0 + 4);
    const float gg[8]  = {ga.x, ga.y, ga.z, ga.w, gb.x, gb.y, gb.z, gb.w};
    const float bbv[8] = {ba.x, ba.y, ba.z, ba.w, bb.x, bb.y, bb.z, bb.w};

    __nv_bfloat162 o[4];
    #pragma unroll
    for (int j = 0; j < 4; j++) {
        o[j].x = __float2bfloat16((v[2*j]   - mean) * inv * gg[2*j]   + bbv[2*j]);
        o[j].y = __float2bfloat16((v[2*j+1] - mean) * inv * gg[2*j+1] + bbv[2*j+1]);
    }
    *reinterpret_cast<uint4*>(&g_h2[(size_t)row * Cdim + c0]) =
        *reinterpret_cast<uint4*>(o);
}

// ---------------------------------------------------------------------------
// Double-buffered GEMM: A bf16 (ldmatrix), B fp32 direct from gmem
// (fragments built via float2 shared loads + cvt -> bf16x2).
//   C[m,n] = sum_k A[m,k]*B[n,k]   (A:[M,K] bf16, B:[N,K] fp32, row-major)
// MODE 0: relu(acc + bias[n]) -> bf16 Cout
// MODE 1: acc + resid[m,n] + bias[n] + bias2[n] -> fp32 Cout
// ---------------------------------------------------------------------------
template <int BM, int BN, int BK, int WM, int WN, int MODE>
__global__ void mma_gemm(const __nv_bfloat16* __restrict__ A,
                         const float* __restrict__ B,
                         void* __restrict__ Cout,
                         int Ktot, int Ntot,
                         const float* __restrict__ bias,
                         const float* __restrict__ resid,
                         const float* __restrict__ bias2)
{
    constexpr int WARPS_M = BM / WM;
    constexpr int WARPS_N = BN / WN;
    constexpr int NT   = WARPS_M * WARPS_N * 32;
    constexpr int LDSA = BK + 8;   // bf16 elems per A smem row (144B, 16B-aligned)
    constexpr int LDSB = BK + 8;   // fp32 elems per B smem row (mod-32 banks = 8 -> conflict-free)
    constexpr int MT   = WM / 16;
    constexpr int NTt  = WN / 8;

    extern __shared__ char smem[];
    __nv_bfloat16* As = reinterpret_cast<__nv_bfloat16*>(smem);
    float*         Bs = reinterpret_cast<float*>(smem + 2 * BM * LDSA * sizeof(__nv_bfloat16));
    // As[buf]: BM*LDSA bf16 each; Bs[buf]: BN*LDSB float each

    const int tid  = threadIdx.x;
    const int lane = tid & 31;
    const int warp = tid >> 5;
    const int wm   = warp / WARPS_N;
    const int wn   = warp % WARPS_N;
    const int m0   = blockIdx.y * BM;
    const int n0   = blockIdx.x * BN;
    const int kIters = Ktot / BK;

    auto load_stage = [&](int buf, int k0) {
        __nv_bfloat16* Ab = As + buf * BM * LDSA;
        float*         Bb = Bs + buf * BN * LDSB;
        #pragma unroll
        for (int i = tid; i < BM * BK / 8; i += NT) {
            const int r = i / (BK / 8), cv = i % (BK / 8);
            cp_async16(smem_u32(&Ab[r * LDSA + cv * 8]),
                       &A[(size_t)(m0 + r) * Ktot + k0 + cv * 8]);
        }
        #pragma unroll
        for (int i = tid; i < BN * BK / 4; i += NT) {
            const int r = i / (BK / 4), cv = i % (BK / 4);
            cp_async16(smem_u32(&Bb[r * LDSB + cv * 4]),
                       &B[(size_t)(n0 + r) * Ktot + k0 + cv * 4]);
        }
        cp_commit();
    };

    float acc[MT][NTt][4];
    #pragma unroll
    for (int i = 0; i < MT; i++)
        #pragma unroll
        for (int j = 0; j < NTt; j++)
            #pragma unroll
            for (int r = 0; r < 4; r++) acc[i][j][r] = 0.f;

    load_stage(0, 0);

    for (int it = 0; it < kIters; it++) {
        const int buf = it & 1;
        if (it + 1 < kIters) {
            load_stage((it + 1) & 1, (it + 1) * BK);
            cp_wait<1>();
        } else {
            cp_wait<0>();
        }
        __syncthreads();

        const __nv_bfloat16* Ab = As + buf * BM * LDSA;
        const float*         Bb = Bs + buf * BN * LDSB;

        #pragma unroll
        for (int ks = 0; ks < BK; ks += 16) {
            uint32_t afrag[MT][4];
            #pragma unroll
            for (int mt = 0; mt < MT; mt++) {
                const int row = wm * WM + mt * 16 + (lane & 15);
                const int col = ks + (lane >> 4) * 8;
                ldsm_x4(afrag[mt][0], afrag[mt][1], afrag[mt][2], afrag[mt][3],
                        smem_u32(&Ab[row * LDSA + col]));
            }
            uint32_t bfrag[NTt][2];
            #pragma unroll
            for (int nt = 0; nt < NTt; nt++) {
                const int row = wn * WN + nt * 8 + (lane >> 2);
                const int col = ks + (lane & 3) * 2;
                const float2 f0 = *reinterpret_cast<const float2*>(&Bb[row * LDSB + col]);
                const float2 f1 = *reinterpret_cast<const float2*>(&Bb[row * LDSB + col + 8]);
                __nv_bfloat162 h0 = __float22bfloat162_rn(f0);   // .x = k even (low)
                __nv_bfloat162 h1 = __float22bfloat162_rn(f1);
                bfrag[nt][0] = *reinterpret_cast<uint32_t*>(&h0);
                bfrag[nt][1] = *reinterpret_cast<uint32_t*>(&h1);
            }
            #pragma unroll
            for (int mt = 0; mt < MT; mt++)
                #pragma unroll
                for (int nt = 0; nt < NTt; nt++)
                    mma_bf16(acc[mt][nt], afrag[mt], bfrag[nt]);
        }
        __syncthreads();
    }

    // Epilogue
    #pragma unroll
    for (int mt = 0; mt < MT; mt++) {
        #pragma unroll
        for (int nt = 0; nt < NTt; nt++) {
            const int m = m0 + wm * WM + mt * 16 + (lane >> 2);
            const int n = n0 + wn * WN + nt * 8 + (lane & 3) * 2;
            float c0 = acc[mt][nt][0], c1 = acc[mt][nt][1];
            float c2 = acc[mt][nt][2], c3 = acc[mt][nt][3];
            if (MODE == 0) {
                const float b0 = bias[n], b1 = bias[n + 1];
                c0 = fmaxf(c0 + b0, 0.f); c1 = fmaxf(c1 + b1, 0.f);
                c2 = fmaxf(c2 + b0, 0.f); c3 = fmaxf(c3 + b1, 0.f);
                __nv_bfloat16* O = (__nv_bfloat16*)Cout;
                __nv_bfloat162 p;
                p.x = __float2bfloat16(c0); p.y = __float2bfloat16(c1);
                *reinterpret_cast<__nv_bfloat162*>(&O[(size_t)m * Ntot + n]) = p;
                p.x = __float2bfloat16(c2); p.y = __float2bfloat16(c3);
                *reinterpret_cast<__nv_bfloat162*>(&O[(size_t)(m + 8) * Ntot + n]) = p;
            } else {
                float* O = (float*)Cout;
                const float b0 = bias[n] + bias2[n];
                const float b1 = bias[n + 1] + bias2[n + 1];
                const float2 r0 = *reinterpret_cast<const float2*>(&resid[(size_t)m * Ntot + n]);
                const float2 r1 = *reinterpret_cast<const float2*>(&resid[(size_t)(m + 8) * Ntot + n]);
                float2 p;
                p.x = c0 + r0.x + b0; p.y = c1 + r0.y + b1;
                *reinterpret_cast<float2*>(&O[(size_t)m * Ntot + n]) = p;
                p.x = c2 + r1.x + b0; p.y = c3 + r1.y + b1;
                *reinterpret_cast<float2*>(&O[(size_t)(m + 8) * Ntot + n]) = p;
            }
        }
    }
}

// ---------------------------------------------------------------------------
// Attention branch is exactly 0 (transform *= 0.0)  =>  sa == bp.
//   y = (x + bp) + relu(LN(x+bp)@W1^T + bf1) @ W2^T + bf2
// Inputs: 0:x 1:Wt 2:Wp 3:bp 4:g1 5:b1 6:g2 7:b2 8:W1 9:bf1 10:W2 11:bf2
// ---------------------------------------------------------------------------
extern "C" void kernel_launch(void* const* d_in, const int* in_sizes, int n_in,
                              void* d_out, int out_size)
{
    const float* x   = (const float*)d_in[0];
    const float* bp  = (const float*)d_in[3];
    const float* g2  = (const float*)d_in[6];
    const float* b2  = (const float*)d_in[7];
    const float* W1  = (const float*)d_in[8];
    const float* bf1 = (const float*)d_in[9];
    const float* W2  = (const float*)d_in[10];
    const float* bf2 = (const float*)d_in[11];
    float* out = (float*)d_out;

    __nv_bfloat16 *h2p, *hidp;
    cudaGetSymbolAddress((void**)&h2p,  g_h2);
    cudaGetSymbolAddress((void**)&hidp, g_hid);

    // GEMM1: BM=64 BN=128 BK=64  -> smem = 2*64*72*2 + 2*128*72*4 = 92160 B
    constexpr int SMEM1 = 2 * 64 * 72 * 2 + 2 * 128 * 72 * 4;
    // GEMM2: BM=64 BN=32 BK=64   -> smem = 2*64*72*2 + 2*32*72*4  = 36864 B
    constexpr int SMEM2 = 2 * 64 * 72 * 2 + 2 * 32 * 72 * 4;

    auto* k1 = mma_gemm<64, 128, 64, 32, 32, 0>;
    auto* k2 = mma_gemm<64, 32, 64, 16, 16, 1>;
    cudaFuncSetAttribute((const void*)k1, cudaFuncAttributeMaxDynamicSharedMemorySize, SMEM1);
    cudaFuncSetAttribute((const void*)k2, cudaFuncAttributeMaxDynamicSharedMemorySize, SMEM2);

    // 1) LN -> bf16 h2  (128 blocks, warp per row)
    ln_kernel<<<Mrows / 8, 256>>>(x, bp, g2, b2);

    // 2) hid = relu(h2 @ W1^T + bf1) : M=1024, N=1024, K=256 -> bf16
    //    grid 8 x 16 = 128 blocks
    k1<<<dim3(Hdim / 128, Mrows / 64), 256, SMEM1>>>(
        h2p, W1, hidp, Cdim, Hdim, bf1, nullptr, nullptr);

    // 3) out = hid @ W2^T + x + bp + bf2 : M=1024, N=256, K=1024 -> fp32
    //    grid 8 x 16 = 128 blocks, no split-K, no reduce
    k2<<<dim3(Cdim / 32, Mrows / 64), 256, SMEM2>>>(
        hidp, W2, out, Hdim, Cdim, bp, x, bf2);
}

// round 5
// speedup vs baseline: 1.1235x; 1.1235x over previous
#include <cuda_runtime.h>
#include <cuda_bf16.h>
#include <cstdint>

// Problem constants (B=2, T=512, C=256, HID=1024)
constexpr int Mrows = 1024;   // B*T
constexpr int Cdim  = 256;
constexpr int Hdim  = 1024;

// Static device scratch
__device__ __nv_bfloat16 g_h2 [Mrows * Cdim];
__device__ __nv_bfloat16 g_hid[Mrows * Hdim];
__device__ __nv_bfloat16 g_W1 [Hdim * Cdim];
__device__ __nv_bfloat16 g_W2 [Cdim * Hdim];

// ---------------------------------------------------------------------------
// PTX helpers
// ---------------------------------------------------------------------------
__device__ __forceinline__ uint32_t smem_u32(const void* p) {
    return (uint32_t)__cvta_generic_to_shared(p);
}
__device__ __forceinline__ void ldsm_x4(uint32_t& r0, uint32_t& r1,
                                        uint32_t& r2, uint32_t& r3, uint32_t a) {
    asm volatile("ldmatrix.sync.aligned.m8n8.x4.shared.b16 {%0,%1,%2,%3},[%4];"
                 : "=r"(r0), "=r"(r1), "=r"(r2), "=r"(r3) : "r"(a));
}
__device__ __forceinline__ void ldsm_x2(uint32_t& r0, uint32_t& r1, uint32_t a) {
    asm volatile("ldmatrix.sync.aligned.m8n8.x2.shared.b16 {%0,%1},[%2];"
                 : "=r"(r0), "=r"(r1) : "r"(a));
}
__device__ __forceinline__ void mma_bf16(float* c, const uint32_t* a, const uint32_t* b) {
    asm volatile(
        "mma.sync.aligned.m16n8k16.row.col.f32.bf16.bf16.f32 "
        "{%0,%1,%2,%3},{%4,%5,%6,%7},{%8,%9},{%0,%1,%2,%3};"
        : "+f"(c[0]), "+f"(c[1]), "+f"(c[2]), "+f"(c[3])
        : "r"(a[0]), "r"(a[1]), "r"(a[2]), "r"(a[3]), "r"(b[0]), "r"(b[1]));
}
__device__ __forceinline__ void cp_async16(uint32_t s, const void* g) {
    asm volatile("cp.async.cg.shared.global [%0], [%1], 16;" :: "r"(s), "l"(g));
}
__device__ __forceinline__ void cp_commit() {
    asm volatile("cp.async.commit_group;");
}
template <int N> __device__ __forceinline__ void cp_wait() {
    asm volatile("cp.async.wait_group %0;" :: "n"(N));
}

// ---------------------------------------------------------------------------
// Fused prep kernel:
//   blocks [0, 512)   : convert W1,W2 fp32 -> bf16 (4 floats per thread)
//   blocks [512, 640) : LN, 8 rows per block (one warp per row)
// ---------------------------------------------------------------------------
__global__ void prep_kernel(const float* __restrict__ W1,
                            const float* __restrict__ W2,
                            const float* __restrict__ x,
                            const float* __restrict__ bp,
                            const float* __restrict__ g2,
                            const float* __restrict__ b2)
{
    if (blockIdx.x < 512) {
        const int i   = blockIdx.x * blockDim.x + threadIdx.x;
        const int idx = i * 4;
        const float* s;
        __nv_bfloat16* d;
        if (idx < Hdim * Cdim) { s = W1 + idx;                 d = g_W1 + idx; }
        else                   { s = W2 + (idx - Hdim * Cdim); d = g_W2 + (idx - Hdim * Cdim); }
        const float4 v = *reinterpret_cast<const float4*>(s);
        __nv_bfloat162 p0, p1;
        p0.x = __float2bfloat16(v.x); p0.y = __float2bfloat16(v.y);
        p1.x = __float2bfloat16(v.z); p1.y = __float2bfloat16(v.w);
        reinterpret_cast<__nv_bfloat162*>(d)[0] = p0;
        reinterpret_cast<__nv_bfloat162*>(d)[1] = p1;
        return;
    }
    // LN part: one warp per row
    const int gtid = (blockIdx.x - 512) * blockDim.x + threadIdx.x;
    const int row  = gtid >> 5;
    const int lane = gtid & 31;
    const int c0   = lane * 8;
    const float* rp = x + (size_t)row * Cdim + c0;

    float v[8];
    {
        const float4 a  = *reinterpret_cast<const float4*>(rp);
        const float4 b  = *reinterpret_cast<const float4*>(rp + 4);
        const float4 pa = *reinterpret_cast<const float4*>(bp + c0);
        const float4 pb = *reinterpret_cast<const float4*>(bp + c0 + 4);
        v[0] = a.x + pa.x; v[1] = a.y + pa.y; v[2] = a.z + pa.z; v[3] = a.w + pa.w;
        v[4] = b.x + pb.x; v[5] = b.y + pb.y; v[6] = b.z + pb.z; v[7] = b.w + pb.w;
    }
    float s = 0.f, q = 0.f;
    #pragma unroll
    for (int j = 0; j < 8; j++) { s += v[j]; q += v[j] * v[j]; }
    #pragma unroll
    for (int o = 16; o > 0; o >>= 1) {
        s += __shfl_xor_sync(0xffffffffu, s, o);
        q += __shfl_xor_sync(0xffffffffu, q, o);
    }
    const float mean = s * (1.0f / Cdim);
    const float var  = q * (1.0f / Cdim) - mean * mean;
    const float inv  = rsqrtf(var + 1e-5f);

    const float4 ga = *reinterpret_cast<const float4*>(g2 + c0);
    const float4 gb = *reinterpret_cast<const float4*>(g2 + c0 + 4);
    const float4 ba = *reinterpret_cast<const float4*>(b2 + c0);
    const float4 bb = *reinterpret_cast<const float4*>(b2 + c0 + 4);
    const float gg[8]  = {ga.x, ga.y, ga.z, ga.w, gb.x, gb.y, gb.z, gb.w};
    const float bbv[8] = {ba.x, ba.y, ba.z, ba.w, bb.x, bb.y, bb.z, bb.w};

    __nv_bfloat162 o[4];
    #pragma unroll
    for (int j = 0; j < 4; j++) {
        o[j].x = __float2bfloat16((v[2*j]   - mean) * inv * gg[2*j]   + bbv[2*j]);
        o[j].y = __float2bfloat16((v[2*j+1] - mean) * inv * gg[2*j+1] + bbv[2*j+1]);
    }
    *reinterpret_cast<uint4*>(&g_h2[(size_t)row * Cdim + c0]) =
        *reinterpret_cast<uint4*>(o);
}

// ---------------------------------------------------------------------------
// Double-buffered cp.async bf16 HMMA GEMM:
//   C[m,n] = sum_k A[m,k]*B[n,k]   (A:[M,K], B:[N,K] bf16 row-major)
// MODE 0: relu(acc + bias[n]) -> bf16 Cout
// MODE 1: acc + resid[m,n] + bias[n] + bias2[n] -> fp32 Cout
// ---------------------------------------------------------------------------
template <int BM, int BN, int BK, int WM, int WN, int MODE>
__global__ void mma_gemm(const __nv_bfloat16* __restrict__ A,
                         const __nv_bfloat16* __restrict__ B,
                         void* __restrict__ Cout,
                         int Ktot, int Ntot,
                         const float* __restrict__ bias,
                         const float* __restrict__ resid,
                         const float* __restrict__ bias2)
{
    constexpr int WARPS_M = BM / WM;
    constexpr int WARPS_N = BN / WN;
    constexpr int NT  = WARPS_M * WARPS_N * 32;
    constexpr int LDS = BK + 8;      // bf16 elems per smem row (16B-aligned rows)
    constexpr int MT  = WM / 16;
    constexpr int NTt = WN / 8;

    __shared__ __nv_bfloat16 As[2][BM * LDS];
    __shared__ __nv_bfloat16 Bs[2][BN * LDS];

    const int tid  = threadIdx.x;
    const int lane = tid & 31;
    const int warp = tid >> 5;
    const int wm   = warp / WARPS_N;
    const int wn   = warp % WARPS_N;
    const int m0   = blockIdx.y * BM;
    const int n0   = blockIdx.x * BN;
    const int kIters = Ktot / BK;

    auto load_stage = [&](int buf, int k0) {
        #pragma unroll
        for (int i = tid; i < BM * BK / 8; i += NT) {
            const int r = i / (BK / 8), cv = i % (BK / 8);
            cp_async16(smem_u32(&As[buf][r * LDS + cv * 8]),
                       &A[(size_t)(m0 + r) * Ktot + k0 + cv * 8]);
        }
        #pragma unroll
        for (int i = tid; i < BN * BK / 8; i += NT) {
            const int r = i / (BK / 8), cv = i % (BK / 8);
            cp_async16(smem_u32(&Bs[buf][r * LDS + cv * 8]),
                       &B[(size_t)(n0 + r) * Ktot + k0 + cv * 8]);
        }
        cp_commit();
    };

    float acc[MT][NTt][4];
    #pragma unroll
    for (int i = 0; i < MT; i++)
        #pragma unroll
        for (int j = 0; j < NTt; j++)
            #pragma unroll
            for (int r = 0; r < 4; r++) acc[i][j][r] = 0.f;

    load_stage(0, 0);

    for (int it = 0; it < kIters; it++) {
        const int buf = it & 1;
        if (it + 1 < kIters) {
            load_stage((it + 1) & 1, (it + 1) * BK);
            cp_wait<1>();
        } else {
            cp_wait<0>();
        }
        __syncthreads();

        #pragma unroll
        for (int ks = 0; ks < BK; ks += 16) {
            uint32_t afrag[MT][4];
            #pragma unroll
            for (int mt = 0; mt < MT; mt++) {
                const int row = wm * WM + mt * 16 + (lane & 15);
                const int col = ks + (lane >> 4) * 8;
                ldsm_x4(afrag[mt][0], afrag[mt][1], afrag[mt][2], afrag[mt][3],
                        smem_u32(&As[buf][row * LDS + col]));
            }
            uint32_t bfrag[NTt][2];
            #pragma unroll
            for (int nt = 0; nt < NTt; nt++) {
                const int row = wn * WN + nt * 8 + (lane & 7);
                const int col = ks + ((lane >> 3) & 1) * 8;
                ldsm_x2(bfrag[nt][0], bfrag[nt][1],
                        smem_u32(&Bs[buf][row * LDS + col]));
            }
            #pragma unroll
            for (int mt = 0; mt < MT; mt++)
                #pragma unroll
                for (int nt = 0; nt < NTt; nt++)
                    mma_bf16(acc[mt][nt], afrag[mt], bfrag[nt]);
        }
        __syncthreads();
    }

    // Epilogue
    #pragma unroll
    for (int mt = 0; mt < MT; mt++) {
        #pragma unroll
        for (int nt = 0; nt < NTt; nt++) {
            const int m = m0 + wm * WM + mt * 16 + (lane >> 2);
            const int n = n0 + wn * WN + nt * 8 + (lane & 3) * 2;
            float c0 = acc[mt][nt][0], c1 = acc[mt][nt][1];
            float c2 = acc[mt][nt][2], c3 = acc[mt][nt][3];
            if (MODE == 0) {
                const float b0 = bias[n], b1 = bias[n + 1];
                c0 = fmaxf(c0 + b0, 0.f); c1 = fmaxf(c1 + b1, 0.f);
                c2 = fmaxf(c2 + b0, 0.f); c3 = fmaxf(c3 + b1, 0.f);
                __nv_bfloat16* O = (__nv_bfloat16*)Cout;
                __nv_bfloat162 p;
                p.x = __float2bfloat16(c0); p.y = __float2bfloat16(c1);
                *reinterpret_cast<__nv_bfloat162*>(&O[(size_t)m * Ntot + n]) = p;
                p.x = __float2bfloat16(c2); p.y = __float2bfloat16(c3);
                *reinterpret_cast<__nv_bfloat162*>(&O[(size_t)(m + 8) * Ntot + n]) = p;
            } else {
                float* O = (float*)Cout;
                const float b0 = bias[n] + bias2[n];
                const float b1 = bias[n + 1] + bias2[n + 1];
                const float2 r0 = *reinterpret_cast<const float2*>(&resid[(size_t)m * Ntot + n]);
                const float2 r1 = *reinterpret_cast<const float2*>(&resid[(size_t)(m + 8) * Ntot + n]);
                float2 p;
                p.x = c0 + r0.x + b0; p.y = c1 + r0.y + b1;
                *reinterpret_cast<float2*>(&O[(size_t)m * Ntot + n]) = p;
                p.x = c2 + r1.x + b0; p.y = c3 + r1.y + b1;
                *reinterpret_cast<float2*>(&O[(size_t)(m + 8) * Ntot + n]) = p;
            }
        }
    }
}

// ---------------------------------------------------------------------------
// Attention branch is exactly 0 (transform *= 0.0)  =>  sa == bp.
//   y = (x + bp) + relu(LN(x+bp)@W1^T + bf1) @ W2^T + bf2
// Inputs: 0:x 1:Wt 2:Wp 3:bp 4:g1 5:b1 6:g2 7:b2 8:W1 9:bf1 10:W2 11:bf2
// ---------------------------------------------------------------------------
extern "C" void kernel_launch(void* const* d_in, const int* in_sizes, int n_in,
                              void* d_out, int out_size)
{
    const float* x   = (const float*)d_in[0];
    const float* bp  = (const float*)d_in[3];
    const float* g2  = (const float*)d_in[6];
    const float* b2  = (const float*)d_in[7];
    const float* W1  = (const float*)d_in[8];
    const float* bf1 = (const float*)d_in[9];
    const float* W2  = (const float*)d_in[10];
    const float* bf2 = (const float*)d_in[11];
    float* out = (float*)d_out;

    __nv_bfloat16 *h2p, *hidp, *w1p, *w2p;
    cudaGetSymbolAddress((void**)&h2p,  g_h2);
    cudaGetSymbolAddress((void**)&hidp, g_hid);
    cudaGetSymbolAddress((void**)&w1p,  g_W1);
    cudaGetSymbolAddress((void**)&w2p,  g_W2);

    // 1) fused: convert W1,W2 -> bf16  +  LN -> bf16 h2
    prep_kernel<<<512 + 128, 256>>>(W1, W2, x, bp, g2, b2);

    // 2) hid = relu(h2 @ W1^T + bf1) : M=1024, N=1024, K=256 -> bf16
    //    grid 8 x 16 = 128 blocks, BK=64 (4 mainloop iters)
    mma_gemm<64, 128, 64, 32, 32, 0>
        <<<dim3(Hdim / 128, Mrows / 64), 256>>>(
            h2p, w1p, hidp, Cdim, Hdim, bf1, nullptr, nullptr);

    // 3) out = hid @ W2^T + x + bp + bf2 : M=1024, N=256, K=1024 -> fp32
    //    grid 8 x 16 = 128 blocks, BK=128 (8 mainloop iters), no split-K
    mma_gemm<64, 32, 128, 16, 16, 1>
        <<<dim3(Cdim / 32, Mrows / 64), 256>>>(
            hidp, w2p, out, Hdim, Cdim, bp, x, bf2);
}